// round 2
// baseline (speedup 1.0000x reference)
#include <cuda_runtime.h>
#include <cstdint>

// Problem constants (fixed by the reference generator)
#define N1MAX 15000
#define N2MAX 60000

// ---------------- device scratch (static __device__ globals; no allocs) ------
__device__ float g_f1s [(N1MAX + 1) * 128];   // feats1 + zero sentinel row
__device__ float g_x   [(N2MAX + 1) * 128];   // concat(x1, feats2) + sentinel
__device__ float g_pre1[ N2MAX      * 64 ];   // conv1 pre-BN
__device__ float g_h   [(N2MAX + 1) * 64 ];   // conv1 post BN+ReLU + sentinel
__device__ int   g_upmap[8 * N2MAX];          // upsample tap->src map
__device__ float g_part [128 * 64 * 2];       // BN partial sums
__device__ float g_bn   [128];                // scale[64], shift[64]

// ---------------- prep kernels ----------------------------------------------
__global__ void prep_upmap_kernel(const int* __restrict__ up_src,
                                  const int* __restrict__ up_kidx,
                                  int n1, int n2)
{
    int idx = blockIdx.x * blockDim.x + threadIdx.x;
    if (idx >= 8 * n2) return;
    int t = idx / n2;
    int i = idx - t * n2;
    g_upmap[idx] = (up_kidx[i] == t) ? up_src[i] : n1;
}

__global__ void prep_f1s_kernel(const float4* __restrict__ feats1, int n1)
{
    int idx = blockIdx.x * blockDim.x + threadIdx.x;     // over (n1+1)*32 float4
    if (idx >= (n1 + 1) * 32) return;
    float4 v = make_float4(0.f, 0.f, 0.f, 0.f);
    if (idx < n1 * 32) v = feats1[idx];
    ((float4*)g_f1s)[idx] = v;
}

__global__ void prep_x_kernel(const float4* __restrict__ feats2, int n2)
{
    int idx = blockIdx.x * blockDim.x + threadIdx.x;     // over n2*16 float4
    if (idx >= n2 * 16) return;
    int r  = idx >> 4;
    int c4 = idx & 15;
    ((float4*)g_x)[r * 32 + 16 + c4] = feats2[idx];      // columns 64..127
}

__global__ void prep_sentinel_kernel(int n2)
{
    int tid = threadIdx.x;
    if (tid < 128) g_x[(size_t)n2 * 128 + tid] = 0.f;
    if (tid < 64)  g_h[(size_t)n2 * 64  + tid] = 0.f;
}

// ---------------- generic gather-conv ---------------------------------------
// out[i, 0:64] = sum over taps t with srcmap[t*n+i] != sentinel of
//                x[srcmap[t*n+i], :] @ w[t]           (w: [ntaps, CI, 64])
//
// Block owns 256 output rows. Per tap: stage w[t] in smem, compact hit rows
// (smem atomic counter; deterministic result since each (row,tap) adds once),
// then dense register-tiled GEMM over compacted rows; accumulate into a
// 256x64 fp32 tile in shared memory.
template <int CI>
__global__ __launch_bounds__(256, 2)
void conv_gather_kernel(const float* __restrict__ x,
                        const float* __restrict__ w,
                        const int*   __restrict__ srcmap,
                        float* __restrict__ out,
                        int n, int ntaps, int sentinel, int ostride)
{
    extern __shared__ float smem[];
    float* accsm = smem;                       // 256*64 floats
    float* ws    = smem + 256 * 64;            // CI*64 floats
    int*   hrow  = (int*)(ws + CI * 64);       // 256 ints
    int*   hsrc  = hrow + 256;                 // 256 ints
    __shared__ int scnt;

    const int tid  = threadIdx.x;
    const int base = blockIdx.x * 256;
    const int wid  = tid >> 5;
    const int lane = tid & 31;
    const int co0  = lane * 2;

    // zero accumulator tile
    float4* a4 = (float4*)accsm;
    #pragma unroll
    for (int i = tid; i < 256 * 16; i += 256)
        a4[i] = make_float4(0.f, 0.f, 0.f, 0.f);

    for (int t = 0; t < ntaps; ++t) {
        __syncthreads();   // previous tap's GEMM / zeroing done
        // stage weights for tap t
        const float4* wt = (const float4*)(w + (size_t)t * CI * 64);
        float4* ws4 = (float4*)ws;
        #pragma unroll
        for (int i = tid; i < CI * 16; i += 256) ws4[i] = wt[i];
        if (tid == 0) scnt = 0;
        __syncthreads();

        // compact hit rows
        {
            int r = base + tid;
            int s = (r < n) ? srcmap[(size_t)t * n + r] : sentinel;
            if (s != sentinel) {
                int p = atomicAdd(&scnt, 1);
                hrow[p] = tid;
                hsrc[p] = s;
            }
        }
        __syncthreads();
        const int nh = scnt;

        // dense GEMM over compacted rows: 4 rows x 2 cols per thread per chunk
        for (int rb = wid * 4; rb < nh; rb += 32) {
            int nr = nh - rb; if (nr > 4) nr = 4;
            const float* xp[4]; int rw[4];
            #pragma unroll
            for (int k = 0; k < 4; ++k) {
                int q = (k < nr) ? (rb + k) : rb;
                xp[k] = x + (size_t)hsrc[q] * CI;
                rw[k] = hrow[q];
            }
            float acc0[4] = {0.f, 0.f, 0.f, 0.f};
            float acc1[4] = {0.f, 0.f, 0.f, 0.f};
            #pragma unroll 4
            for (int c4 = 0; c4 < CI / 4; ++c4) {
                const int c = c4 * 4;
                float2 w0 = *(const float2*)(ws + (c + 0) * 64 + co0);
                float2 w1 = *(const float2*)(ws + (c + 1) * 64 + co0);
                float2 w2 = *(const float2*)(ws + (c + 2) * 64 + co0);
                float2 w3 = *(const float2*)(ws + (c + 3) * 64 + co0);
                #pragma unroll
                for (int k = 0; k < 4; ++k) {
                    if (k >= nr) break;
                    float4 xv = *(const float4*)(xp[k] + c);
                    acc0[k] = fmaf(xv.x, w0.x, acc0[k]);
                    acc0[k] = fmaf(xv.y, w1.x, acc0[k]);
                    acc0[k] = fmaf(xv.z, w2.x, acc0[k]);
                    acc0[k] = fmaf(xv.w, w3.x, acc0[k]);
                    acc1[k] = fmaf(xv.x, w0.y, acc1[k]);
                    acc1[k] = fmaf(xv.y, w1.y, acc1[k]);
                    acc1[k] = fmaf(xv.z, w2.y, acc1[k]);
                    acc1[k] = fmaf(xv.w, w3.y, acc1[k]);
                }
            }
            #pragma unroll
            for (int k = 0; k < 4; ++k) {
                if (k >= nr) break;
                float* ap = accsm + rw[k] * 64 + co0;
                ap[0] += acc0[k];
                ap[1] += acc1[k];
            }
        }
    }
    __syncthreads();

    // write tile to global
    for (int i = tid; i < 256 * 16; i += 256) {
        int rr = i >> 4, c4 = i & 15;
        int row = base + rr;
        if (row < n)
            *(float4*)(out + (size_t)row * ostride + c4 * 4) = a4[i];
    }
}

// ---------------- BatchNorm (training mode, biased var) + ReLU ---------------
__global__ void bn_stats_kernel(const float* __restrict__ pre, int n, int stride)
{
    const int tid = threadIdx.x;
    const int c  = tid & 63;
    const int rl = tid >> 6;
    float s = 0.f, s2 = 0.f;
    for (int r = blockIdx.x * 4 + rl; r < n; r += gridDim.x * 4) {
        float v = pre[(size_t)r * stride + c];
        s += v;
        s2 = fmaf(v, v, s2);
    }
    __shared__ float sh[512];
    sh[tid] = s; sh[256 + tid] = s2;
    __syncthreads();
    if (tid < 64) {
        float ts = sh[tid] + sh[64 + tid] + sh[128 + tid] + sh[192 + tid];
        float t2 = sh[256 + tid] + sh[320 + tid] + sh[384 + tid] + sh[448 + tid];
        g_part[(blockIdx.x * 64 + tid) * 2]     = ts;
        g_part[(blockIdx.x * 64 + tid) * 2 + 1] = t2;
    }
}

__global__ void bn_final_kernel(int nblocks, int n,
                                const float* __restrict__ gamma,
                                const float* __restrict__ beta)
{
    int c = threadIdx.x;
    if (c >= 64) return;
    float s = 0.f, s2 = 0.f;
    for (int g = 0; g < nblocks; ++g) {
        s  += g_part[(g * 64 + c) * 2];
        s2 += g_part[(g * 64 + c) * 2 + 1];
    }
    float invn = 1.f / (float)n;
    float mean = s * invn;
    float var  = s2 * invn - mean * mean;
    float inv  = rsqrtf(var + 1e-5f);
    float scale = gamma[c] * inv;
    g_bn[c]      = scale;
    g_bn[64 + c] = beta[c] - mean * scale;
}

__global__ void bn_apply_kernel(const float* __restrict__ pre, int n, int istride,
                                float* __restrict__ out, int ostride)
{
    int idx = blockIdx.x * blockDim.x + threadIdx.x;
    if (idx >= n * 64) return;
    int r = idx >> 6, c = idx & 63;
    float v = pre[(size_t)r * istride + c];
    v = fmaf(v, g_bn[c], g_bn[64 + c]);
    out[(size_t)r * ostride + c] = fmaxf(v, 0.f);
}

// ---------------- launch ------------------------------------------------------
extern "C" void kernel_launch(void* const* d_in, const int* in_sizes, int n_in,
                              void* d_out, int out_size)
{
    const float* feats1   = (const float*)d_in[0];
    const float* feats2   = (const float*)d_in[1];
    const float* w_up     = (const float*)d_in[2];
    const float* gamma_up = (const float*)d_in[3];
    const float* beta_up  = (const float*)d_in[4];
    const float* w1       = (const float*)d_in[5];
    const float* gamma1   = (const float*)d_in[6];
    const float* beta1    = (const float*)d_in[7];
    const float* w2       = (const float*)d_in[8];
    const float* gamma2   = (const float*)d_in[9];
    const float* beta2    = (const float*)d_in[10];
    const int*   up_src   = (const int*)d_in[11];
    const int*   up_kidx  = (const int*)d_in[12];
    const int*   nbr_src  = (const int*)d_in[13];
    float*       out      = (float*)d_out;

    const int n1 = in_sizes[0] / 128;
    const int n2 = in_sizes[1] / 64;

    float *f1s, *x, *pre1, *h;
    int* upmap;
    cudaGetSymbolAddress((void**)&f1s,   g_f1s);
    cudaGetSymbolAddress((void**)&x,     g_x);
    cudaGetSymbolAddress((void**)&pre1,  g_pre1);
    cudaGetSymbolAddress((void**)&h,     g_h);
    cudaGetSymbolAddress((void**)&upmap, g_upmap);

    const int SM128 = 256 * 64 * 4 + 128 * 64 * 4 + 2 * 256 * 4;  // 100352 B
    const int SM64  = 256 * 64 * 4 +  64 * 64 * 4 + 2 * 256 * 4;  //  83968 B
    cudaFuncSetAttribute(conv_gather_kernel<128>,
                         cudaFuncAttributeMaxDynamicSharedMemorySize, SM128);
    cudaFuncSetAttribute(conv_gather_kernel<64>,
                         cudaFuncAttributeMaxDynamicSharedMemorySize, SM64);

    const int nbConv = (n2 + 255) / 256;
    const int G = 128;                       // BN stats blocks
    const int nbApply = (n2 * 64 + 255) / 256;

    // prep
    prep_upmap_kernel<<<(8 * n2 + 255) / 256, 256>>>(up_src, up_kidx, n1, n2);
    prep_f1s_kernel<<<((n1 + 1) * 32 + 255) / 256, 256>>>((const float4*)feats1, n1);
    prep_x_kernel<<<(n2 * 16 + 255) / 256, 256>>>((const float4*)feats2, n2);
    prep_sentinel_kernel<<<1, 128>>>(n2);

    // upsample (8-tap gather conv, feats1 -> x[:,0:64]) + BN + ReLU (in place)
    conv_gather_kernel<128><<<nbConv, 256, SM128>>>(f1s, w_up, upmap, x,
                                                    n2, 8, n1, 128);
    bn_stats_kernel<<<G, 256>>>(x, n2, 128);
    bn_final_kernel<<<1, 64>>>(G, n2, gamma_up, beta_up);
    bn_apply_kernel<<<nbApply, 256>>>(x, n2, 128, x, 128);

    // conv1 (27-tap, CI=128) + BN + ReLU -> h
    conv_gather_kernel<128><<<nbConv, 256, SM128>>>(x, w1, nbr_src, pre1,
                                                    n2, 27, n2, 64);
    bn_stats_kernel<<<G, 256>>>(pre1, n2, 64);
    bn_final_kernel<<<1, 64>>>(G, n2, gamma1, beta1);
    bn_apply_kernel<<<nbApply, 256>>>(pre1, n2, 64, h, 64);

    // conv2 (27-tap, CI=64) + BN + ReLU -> d_out (in place)
    conv_gather_kernel<64><<<nbConv, 256, SM64>>>(h, w2, nbr_src, out,
                                                  n2, 27, n2, 64);
    bn_stats_kernel<<<G, 256>>>(out, n2, 64);
    bn_final_kernel<<<1, 64>>>(G, n2, gamma2, beta2);
    bn_apply_kernel<<<nbApply, 256>>>(out, n2, 64, out, 64);
}

// round 3
// speedup vs baseline: 2.3327x; 2.3327x over previous
#include <cuda_runtime.h>
#include <cstdint>

// Problem constants (fixed by the reference generator)
#define N1MAX 15000
#define N2MAX 60000

// ---------------- device scratch (static __device__ globals; no allocs) ------
__device__ float g_f1s [(N1MAX + 1) * 128];   // feats1 + zero sentinel row
__device__ float g_x   [(N2MAX + 1) * 128];   // concat(x1, feats2) + sentinel
__device__ float g_pre1[ N2MAX      * 64 ];   // conv1 pre-BN
__device__ float g_h   [(N2MAX + 1) * 64 ];   // conv1 post BN+ReLU + sentinel
__device__ int   g_upmap[8 * N2MAX];          // upsample tap->src map
__device__ float g_part [256 * 64 * 2];       // per-block BN partial sums

// ---------------- fused prep kernel ------------------------------------------
__global__ void prep_all_kernel(const int* __restrict__ up_src,
                                const int* __restrict__ up_kidx,
                                const float4* __restrict__ feats1,
                                const float4* __restrict__ feats2,
                                int n1, int n2)
{
    const int T1 = 8 * n2;            // upmap entries
    const int T2 = (n1 + 1) * 32;     // f1s float4 (incl. sentinel row)
    const int T3 = n2 * 16;           // feats2 float4 into g_x cols 64..127
    const int T4 = 32 + 16;           // sentinel rows of g_x / g_h (float4)
    const int total = T1 + T2 + T3 + T4;
    for (int idx = blockIdx.x * blockDim.x + threadIdx.x; idx < total;
         idx += gridDim.x * blockDim.x) {
        if (idx < T1) {
            int t = idx / n2;
            int i = idx - t * n2;
            g_upmap[idx] = (up_kidx[i] == t) ? up_src[i] : n1;
        } else if (idx < T1 + T2) {
            int j = idx - T1;
            float4 v = make_float4(0.f, 0.f, 0.f, 0.f);
            if (j < n1 * 32) v = feats1[j];
            ((float4*)g_f1s)[j] = v;
        } else if (idx < T1 + T2 + T3) {
            int j = idx - T1 - T2;
            int r = j >> 4, c4 = j & 15;
            ((float4*)g_x)[r * 32 + 16 + c4] = feats2[j];
        } else {
            int j = idx - T1 - T2 - T3;
            float4 z = make_float4(0.f, 0.f, 0.f, 0.f);
            if (j < 32) ((float4*)g_x)[(size_t)n2 * 32 + j] = z;
            else        ((float4*)g_h)[(size_t)n2 * 16 + (j - 32)] = z;
        }
    }
}

// ---------------- generic gather-conv with fused BN partial stats ------------
// out[i, 0:64] = sum over taps t with srcmap[t*n+i] != sentinel of
//                x[srcmap[t*n+i], :] @ w[t]           (w: [ntaps, CI, 64])
// Also writes per-block (sum, sumsq) per column into g_part[blockIdx].
template <int CI>
__global__ __launch_bounds__(256, 2)
void conv_gather_kernel(const float* __restrict__ x,
                        const float* __restrict__ w,
                        const int*   __restrict__ srcmap,
                        float* __restrict__ out,
                        int n, int ntaps, int sentinel, int ostride)
{
    extern __shared__ float smem[];
    float* accsm = smem;                       // 256*64 floats
    float* ws    = smem + 256 * 64;            // CI*64 floats (reused for BN red)
    int*   hrow  = (int*)(ws + CI * 64);       // 256 ints
    int*   hsrc  = hrow + 256;                 // 256 ints
    __shared__ int scnt;

    const int tid  = threadIdx.x;
    const int base = blockIdx.x * 256;
    const int wid  = tid >> 5;
    const int lane = tid & 31;
    const int half = lane >> 4;                // 0/1: which row-quad in warp
    const int cq   = lane & 15;                // col quad index (cols cq*4..cq*4+3)

    // zero accumulator tile
    float4* a4 = (float4*)accsm;
    #pragma unroll
    for (int i = tid; i < 256 * 16; i += 256)
        a4[i] = make_float4(0.f, 0.f, 0.f, 0.f);

    float4* ws4 = (float4*)ws;

    for (int t = 0; t < ntaps; ++t) {
        __syncthreads();   // previous tap's GEMM done; ws/hrow reusable
        // stage weights for tap t
        const float4* wt = (const float4*)(w + (size_t)t * CI * 64);
        #pragma unroll
        for (int i = tid; i < CI * 16; i += 256) ws4[i] = wt[i];
        if (tid == 0) scnt = 0;
        __syncthreads();

        // compact hit rows (order nondeterministic, but one add per (row,tap)
        // in fixed tap order -> deterministic accumulation values)
        {
            int r = base + tid;
            int s = (r < n) ? srcmap[(size_t)t * n + r] : sentinel;
            if (s != sentinel) {
                int p = atomicAdd(&scnt, 1);
                hrow[p] = tid;
                hsrc[p] = s;
            }
        }
        __syncthreads();
        const int nh = scnt;
        if (nh == 0) continue;

        // dense GEMM over compacted rows: half-warp owns 4 rows, 16 lanes x 4 cols
        for (int rb = wid * 8 + half * 4; rb < nh; rb += 64) {
            const float4* xp[4]; int rw[4]; bool vld[4];
            #pragma unroll
            for (int k = 0; k < 4; ++k) {
                int q  = rb + k;
                vld[k] = (q < nh);
                int qc = vld[k] ? q : (nh - 1);
                xp[k]  = (const float4*)(x + (size_t)hsrc[qc] * CI);
                rw[k]  = hrow[qc];
            }
            float4 acc[4];
            #pragma unroll
            for (int k = 0; k < 4; ++k) acc[k] = make_float4(0.f, 0.f, 0.f, 0.f);

            #pragma unroll 4
            for (int c4 = 0; c4 < CI / 4; ++c4) {
                const int c = c4 * 4;
                float4 w0 = ws4[(c + 0) * 16 + cq];
                float4 w1 = ws4[(c + 1) * 16 + cq];
                float4 w2 = ws4[(c + 2) * 16 + cq];
                float4 w3 = ws4[(c + 3) * 16 + cq];
                #pragma unroll
                for (int k = 0; k < 4; ++k) {
                    float4 xv = xp[k][c4];
                    acc[k].x = fmaf(xv.x, w0.x, acc[k].x);
                    acc[k].y = fmaf(xv.x, w0.y, acc[k].y);
                    acc[k].z = fmaf(xv.x, w0.z, acc[k].z);
                    acc[k].w = fmaf(xv.x, w0.w, acc[k].w);
                    acc[k].x = fmaf(xv.y, w1.x, acc[k].x);
                    acc[k].y = fmaf(xv.y, w1.y, acc[k].y);
                    acc[k].z = fmaf(xv.y, w1.z, acc[k].z);
                    acc[k].w = fmaf(xv.y, w1.w, acc[k].w);
                    acc[k].x = fmaf(xv.z, w2.x, acc[k].x);
                    acc[k].y = fmaf(xv.z, w2.y, acc[k].y);
                    acc[k].z = fmaf(xv.z, w2.z, acc[k].z);
                    acc[k].w = fmaf(xv.z, w2.w, acc[k].w);
                    acc[k].x = fmaf(xv.w, w3.x, acc[k].x);
                    acc[k].y = fmaf(xv.w, w3.y, acc[k].y);
                    acc[k].z = fmaf(xv.w, w3.z, acc[k].z);
                    acc[k].w = fmaf(xv.w, w3.w, acc[k].w);
                }
            }
            #pragma unroll
            for (int k = 0; k < 4; ++k) {
                if (vld[k]) {
                    float4* ap = (float4*)(accsm + rw[k] * 64) + cq;
                    float4 v = *ap;
                    v.x += acc[k].x; v.y += acc[k].y;
                    v.z += acc[k].z; v.w += acc[k].w;
                    *ap = v;
                }
            }
        }
    }
    __syncthreads();

    // write tile to global
    for (int i = tid; i < 256 * 16; i += 256) {
        int rr = i >> 4, c4 = i & 15;
        int row = base + rr;
        if (row < n)
            *(float4*)(out + (size_t)row * ostride + c4 * 4) = a4[i];
    }

    // fused BN partial stats from the smem tile (rows >= n are zero)
    {
        const int c  = tid & 63;
        const int rl = tid >> 6;
        float s = 0.f, s2 = 0.f;
        #pragma unroll 4
        for (int r = rl; r < 256; r += 4) {
            float v = accsm[r * 64 + c];
            s += v;
            s2 = fmaf(v, v, s2);
        }
        float* red = ws;   // reuse weight staging area
        __syncthreads();
        red[tid] = s; red[256 + tid] = s2;
        __syncthreads();
        if (tid < 64) {
            float ts = red[tid] + red[64 + tid] + red[128 + tid] + red[192 + tid];
            float t2 = red[256 + tid] + red[320 + tid] + red[384 + tid] + red[448 + tid];
            g_part[(blockIdx.x * 64 + tid) * 2]     = ts;
            g_part[(blockIdx.x * 64 + tid) * 2 + 1] = t2;
        }
    }
}

// ---------------- fused BN finalize + apply + ReLU ----------------------------
__global__ void bn_apply_kernel(const float* __restrict__ pre, int n, int istride,
                                float* __restrict__ out, int ostride,
                                const float* __restrict__ gamma,
                                const float* __restrict__ beta, int nparts)
{
    const int tid = threadIdx.x;
    const int c   = tid & 63;
    float s = 0.f, s2 = 0.f;
    for (int g = 0; g < nparts; ++g) {
        s  += g_part[(g * 64 + c) * 2];
        s2 += g_part[(g * 64 + c) * 2 + 1];
    }
    const float invn  = 1.f / (float)n;
    const float mean  = s * invn;
    const float var   = s2 * invn - mean * mean;
    const float inv   = rsqrtf(var + 1e-5f);
    const float scale = gamma[c] * inv;
    const float shift = beta[c] - mean * scale;

    const int rstep = gridDim.x * 4;
    for (int r = blockIdx.x * 4 + (tid >> 6); r < n; r += rstep) {
        float v = pre[(size_t)r * istride + c];
        v = fmaf(v, scale, shift);
        out[(size_t)r * ostride + c] = fmaxf(v, 0.f);
    }
}

// ---------------- launch ------------------------------------------------------
extern "C" void kernel_launch(void* const* d_in, const int* in_sizes, int n_in,
                              void* d_out, int out_size)
{
    const float* feats1   = (const float*)d_in[0];
    const float* feats2   = (const float*)d_in[1];
    const float* w_up     = (const float*)d_in[2];
    const float* gamma_up = (const float*)d_in[3];
    const float* beta_up  = (const float*)d_in[4];
    const float* w1       = (const float*)d_in[5];
    const float* gamma1   = (const float*)d_in[6];
    const float* beta1    = (const float*)d_in[7];
    const float* w2       = (const float*)d_in[8];
    const float* gamma2   = (const float*)d_in[9];
    const float* beta2    = (const float*)d_in[10];
    const int*   up_src   = (const int*)d_in[11];
    const int*   up_kidx  = (const int*)d_in[12];
    const int*   nbr_src  = (const int*)d_in[13];
    float*       out      = (float*)d_out;

    const int n1 = in_sizes[0] / 128;
    const int n2 = in_sizes[1] / 64;

    float *f1s, *x, *pre1, *h;
    int* upmap;
    cudaGetSymbolAddress((void**)&f1s,   g_f1s);
    cudaGetSymbolAddress((void**)&x,     g_x);
    cudaGetSymbolAddress((void**)&pre1,  g_pre1);
    cudaGetSymbolAddress((void**)&h,     g_h);
    cudaGetSymbolAddress((void**)&upmap, g_upmap);

    const int SM128 = 256 * 64 * 4 + 128 * 64 * 4 + 2 * 256 * 4;  // 100352 B
    const int SM64  = 256 * 64 * 4 +  64 * 64 * 4 + 2 * 256 * 4;  //  83968 B
    cudaFuncSetAttribute(conv_gather_kernel<128>,
                         cudaFuncAttributeMaxDynamicSharedMemorySize, SM128);
    cudaFuncSetAttribute(conv_gather_kernel<64>,
                         cudaFuncAttributeMaxDynamicSharedMemorySize, SM64);

    const int nbConv = (n2 + 255) / 256;    // 235 blocks -> g_part fits 256
    const int nbApply = 256;

    // 0: fused prep
    prep_all_kernel<<<1024, 256>>>(up_src, up_kidx,
                                   (const float4*)feats1, (const float4*)feats2,
                                   n1, n2);

    // 1: upsample (8-tap gather conv, feats1 -> x[:,0:64]) with fused stats
    conv_gather_kernel<128><<<nbConv, 256, SM128>>>(f1s, w_up, upmap, x,
                                                    n2, 8, n1, 128);
    // 2: BN finalize + apply + ReLU (in place on x[:,0:64])
    bn_apply_kernel<<<nbApply, 256>>>(x, n2, 128, x, 128,
                                      gamma_up, beta_up, nbConv);

    // 3: conv1 (27-tap, CI=128) with fused stats -> pre1
    conv_gather_kernel<128><<<nbConv, 256, SM128>>>(x, w1, nbr_src, pre1,
                                                    n2, 27, n2, 64);
    // 4: BN finalize + apply -> h
    bn_apply_kernel<<<nbApply, 256>>>(pre1, n2, 64, h, 64,
                                      gamma1, beta1, nbConv);

    // 5: conv2 (27-tap, CI=64) with fused stats -> d_out
    conv_gather_kernel<64><<<nbConv, 256, SM64>>>(h, w2, nbr_src, out,
                                                  n2, 27, n2, 64);
    // 6: BN finalize + apply (in place on d_out)
    bn_apply_kernel<<<nbApply, 256>>>(out, n2, 64, out, 64,
                                      gamma2, beta2, nbConv);
}

// round 5
// speedup vs baseline: 2.3731x; 1.0173x over previous
#include <cuda_runtime.h>
#include <cuda_bf16.h>
#include <cstdint>

#define N1MAX 15000
#define N2MAX 60000

// ---------------- device scratch (static, no allocs) -------------------------
__device__ float g_x   [N2MAX * 128];                 // concat(x1, feats2)
__device__ float g_h   [N2MAX * 64];                  // conv1 post BN+ReLU
__device__ float g_pre [N2MAX * 64];                  // conv1 pre-BN
__device__ float g_msg [27u * N2MAX * 64];            // per-entry MMA outputs
__device__ int   g_ent  [27 * N2MAX];                 // per-tap compacted src
__device__ int   g_entup[ 8 * N2MAX];
__device__ int   g_pos  [27 * N2MAX];                 // (tap,i) -> slot or -1
__device__ int   g_posup[N2MAX];
__device__ int   g_cnt  [27];
__device__ int   g_cntup[8];
// weight images: [t][part(hi,lo)][o(64)][k(CI)] bf16, k contiguous
__device__ unsigned short g_Bup[8  * 2 * 64 * 128];
__device__ unsigned short g_B1 [27 * 2 * 64 * 128];
__device__ unsigned short g_B2 [27 * 2 * 64 * 64];
__device__ float g_part[256 * 64 * 2];                // BN partials

// ---------------- prep: zero counters, feats2->x, weight split/transpose -----
__device__ __forceinline__ void wsplit_one(const float* __restrict__ w,
                                           unsigned short* __restrict__ dst,
                                           int j, int CI) {
    int per = CI * 64;
    int t = j / per;
    int r = j - t * per;
    int k = r >> 6;          // input channel
    int o = r & 63;          // output channel
    float v = w[j];
    __nv_bfloat16 h = __float2bfloat16(v);
    __nv_bfloat16 l = __float2bfloat16(v - __bfloat162float(h));
    unsigned short* base = dst + (size_t)t * (2 * 64 * CI);
    base[o * CI + k]           = *(unsigned short*)&h;
    base[64 * CI + o * CI + k] = *(unsigned short*)&l;
}

__global__ void prep_kernel(const float4* __restrict__ feats2,
                            const float* __restrict__ wup,
                            const float* __restrict__ w1,
                            const float* __restrict__ w2, int n2)
{
    const int T0 = 35;
    const int T1 = n2 * 16;
    const int T2 = 8  * 128 * 64;
    const int T3 = 27 * 128 * 64;
    const int T4 = 27 * 64  * 64;
    const int total = T0 + T1 + T2 + T3 + T4;
    for (int idx = blockIdx.x * blockDim.x + threadIdx.x; idx < total;
         idx += gridDim.x * blockDim.x) {
        if (idx < T0) {
            if (idx < 27) g_cnt[idx] = 0; else g_cntup[idx - 27] = 0;
        } else if (idx < T0 + T1) {
            int j = idx - T0;
            ((float4*)g_x)[(size_t)(j >> 4) * 32 + 16 + (j & 15)] = feats2[j];
        } else if (idx < T0 + T1 + T2) {
            wsplit_one(wup, g_Bup, idx - T0 - T1, 128);
        } else if (idx < T0 + T1 + T2 + T3) {
            wsplit_one(w1, g_B1, idx - T0 - T1 - T2, 128);
        } else {
            wsplit_one(w2, g_B2, idx - T0 - T1 - T2 - T3, 64);
        }
    }
}

// ---------------- compaction fill kernels ------------------------------------
__global__ void fill_up_kernel(const int* __restrict__ up_src,
                               const int* __restrict__ up_kidx, int n2)
{
    __shared__ int sc[8], sb[8];
    int tid = threadIdx.x;
    int i = blockIdx.x * 256 + tid;
    if (tid < 8) sc[tid] = 0;
    __syncthreads();
    int t = 0, p = 0, s = 0;
    bool v = (i < n2);
    if (v) { t = up_kidx[i]; s = up_src[i]; p = atomicAdd(&sc[t], 1); }
    __syncthreads();
    if (tid < 8 && sc[tid] > 0) sb[tid] = atomicAdd(&g_cntup[tid], sc[tid]);
    __syncthreads();
    if (v) {
        int q = sb[t] + p;
        g_entup[t * n2 + q] = s;
        g_posup[i] = t * n2 + q;
    }
}

__global__ void fill_nbr_kernel(const int* __restrict__ nbr_src, int n2)
{
    __shared__ int sc[27], sb[27];
    int tid = threadIdx.x;
    int j = blockIdx.x * 256 + tid;
    if (tid < 27) sc[tid] = 0;
    __syncthreads();
    int t = 0, p = 0, s = 0;
    bool inr = (j < 27 * n2), hit = false;
    if (inr) {
        t = j / n2;
        s = nbr_src[j];
        hit = (s != n2);
        if (hit) p = atomicAdd(&sc[t], 1);
    }
    __syncthreads();
    if (tid < 27 && sc[tid] > 0) sb[tid] = atomicAdd(&g_cnt[tid], sc[tid]);
    __syncthreads();
    if (inr) {
        if (hit) {
            int q = sb[t] + p;
            g_ent[t * n2 + q] = s;
            g_pos[j] = t * n2 + q;
        } else g_pos[j] = -1;
    }
}

// ---------------- mma.sync helper --------------------------------------------
__device__ __forceinline__ void mma16816(float& c0, float& c1, float& c2, float& c3,
                                         uint32_t a0, uint32_t a1, uint32_t a2, uint32_t a3,
                                         uint32_t b0, uint32_t b1)
{
    asm volatile("mma.sync.aligned.m16n8k16.row.col.f32.bf16.bf16.f32 "
                 "{%0,%1,%2,%3}, {%4,%5,%6,%7}, {%8,%9}, {%0,%1,%2,%3};"
                 : "+f"(c0), "+f"(c1), "+f"(c2), "+f"(c3)
                 : "r"(a0), "r"(a1), "r"(a2), "r"(a3), "r"(b0), "r"(b1));
}

__device__ __forceinline__ uint32_t bits2(__nv_bfloat162 v) {
    return *(uint32_t*)&v;
}

// ---------------- phase A: per-tap dense MMA over compacted entries ----------
// Block = 128 rows x 64 cols for one tap tile. bf16 hi/lo 3-term split,
// fp32 accum via mma.sync.m16n8k16. Rows padded to CI+8 bf16 in smem so
// fragment lds is bank-conflict-free (row stride 272B -> bank 4g+tg distinct).
template <int CI>
__global__ __launch_bounds__(256)
void conv_mma_kernel(const float* __restrict__ xsrc,
                     const unsigned short* __restrict__ btile,
                     const int* __restrict__ ent,
                     const int* __restrict__ cnt,
                     float* __restrict__ msg, int n2)
{
    const int t    = blockIdx.y;
    const int c_t  = cnt[t];
    const int base = blockIdx.x * 128;
    if (base >= c_t) return;
    const int nv = min(128, c_t - base);

    constexpr int AST = CI + 8;                  // padded row stride (bf16)
    extern __shared__ unsigned short smem[];
    unsigned short* Ah = smem;                   // [128][AST]
    unsigned short* Al = Ah + 128 * AST;
    unsigned short* Bh = Al + 128 * AST;         // [64][AST]
    unsigned short* Bl = Bh + 64 * AST;
    int* esm = (int*)(Bl + 64 * AST);            // [128]

    const int tid = threadIdx.x, wid = tid >> 5, lane = tid & 31;
    const int gp = lane >> 2, tg = lane & 3;

    // stage B: gmem image rows [o][k] -> padded smem rows (both parts)
    {
        constexpr int R8 = CI / 8;               // uint4 per row
        const uint4* src = (const uint4*)(btile + (size_t)t * (2 * 64 * CI));
        #pragma unroll
        for (int i = tid; i < 64 * R8; i += 256) {
            int o = i / R8, q = i - (i / R8) * R8;
            *(uint4*)(Bh + o * AST + q * 8) = src[i];
            *(uint4*)(Bl + o * AST + q * 8) = src[64 * R8 + i];
        }
    }
    if (tid < 128) esm[tid] = ent[(size_t)t * n2 + base + min(tid, nv - 1)];
    __syncthreads();

    // gather + bf16 hi/lo split of A rows
    {
        const float4* x4 = (const float4*)xsrc;
        constexpr int C4 = CI / 4;
        #pragma unroll
        for (int i = tid; i < 128 * C4; i += 256) {
            int m = i / C4, q = i - (i / C4) * C4;
            float4 v = __ldg(&x4[(size_t)esm[m] * C4 + q]);
            __nv_bfloat162 h01 = __floats2bfloat162_rn(v.x, v.y);
            __nv_bfloat162 h23 = __floats2bfloat162_rn(v.z, v.w);
            float2 f01 = __bfloat1622float2(h01);
            float2 f23 = __bfloat1622float2(h23);
            __nv_bfloat162 l01 = __floats2bfloat162_rn(v.x - f01.x, v.y - f01.y);
            __nv_bfloat162 l23 = __floats2bfloat162_rn(v.z - f23.x, v.w - f23.y);
            *(uint2*)(Ah + m * AST + q * 4) = make_uint2(bits2(h01), bits2(h23));
            *(uint2*)(Al + m * AST + q * 4) = make_uint2(bits2(l01), bits2(l23));
        }
    }
    __syncthreads();

    // warp computes rows [wid*16, wid*16+16) x all 64 cols
    float acc[8][4];
    #pragma unroll
    for (int nt = 0; nt < 8; ++nt)
        #pragma unroll
        for (int j = 0; j < 4; ++j) acc[nt][j] = 0.f;

    const int rowA = wid * 16 + gp;
    const unsigned short* ah0 = Ah + rowA * AST + tg * 2;
    const unsigned short* ah1 = ah0 + 8 * AST;
    const unsigned short* al0 = Al + rowA * AST + tg * 2;
    const unsigned short* al1 = al0 + 8 * AST;

    #pragma unroll
    for (int s = 0; s < CI / 16; ++s) {
        const int kb = s * 16;
        uint32_t Ah0 = *(const uint32_t*)(ah0 + kb);
        uint32_t Ah1 = *(const uint32_t*)(ah1 + kb);
        uint32_t Ah2 = *(const uint32_t*)(ah0 + kb + 8);
        uint32_t Ah3 = *(const uint32_t*)(ah1 + kb + 8);
        uint32_t Al0 = *(const uint32_t*)(al0 + kb);
        uint32_t Al1 = *(const uint32_t*)(al1 + kb);
        uint32_t Al2 = *(const uint32_t*)(al0 + kb + 8);
        uint32_t Al3 = *(const uint32_t*)(al1 + kb + 8);
        #pragma unroll
        for (int nt = 0; nt < 8; ++nt) {
            const unsigned short* bh = Bh + (nt * 8 + gp) * AST + kb + tg * 2;
            const unsigned short* bl = Bl + (nt * 8 + gp) * AST + kb + tg * 2;
            uint32_t Bh0 = *(const uint32_t*)bh;
            uint32_t Bh1 = *(const uint32_t*)(bh + 8);
            uint32_t Bl0 = *(const uint32_t*)bl;
            uint32_t Bl1 = *(const uint32_t*)(bl + 8);
            mma16816(acc[nt][0], acc[nt][1], acc[nt][2], acc[nt][3],
                     Ah0, Ah1, Ah2, Ah3, Bh0, Bh1);
            mma16816(acc[nt][0], acc[nt][1], acc[nt][2], acc[nt][3],
                     Ah0, Ah1, Ah2, Ah3, Bl0, Bl1);
            mma16816(acc[nt][0], acc[nt][1], acc[nt][2], acc[nt][3],
                     Al0, Al1, Al2, Al3, Bh0, Bh1);
        }
    }

    // epilogue: write compacted msg rows
    {
        int m0 = wid * 16 + gp;
        int m1 = m0 + 8;
        float* d0 = msg + (size_t)(t * n2 + base + m0) * 64 + tg * 2;
        float* d1 = msg + (size_t)(t * n2 + base + m1) * 64 + tg * 2;
        bool v0 = (m0 < nv), v1 = (m1 < nv);
        #pragma unroll
        for (int nt = 0; nt < 8; ++nt) {
            if (v0) *(float2*)(d0 + nt * 8) = make_float2(acc[nt][0], acc[nt][1]);
            if (v1) *(float2*)(d1 + nt * 8) = make_float2(acc[nt][2], acc[nt][3]);
        }
    }
}

// ---------------- phase B: gather-sum over taps + fused BN partials ----------
__global__ __launch_bounds__(256)
void conv_sum_kernel(const float4* __restrict__ msg4, const int* __restrict__ pos,
                     int ntaps, float* __restrict__ pre, int n2)
{
    __shared__ float red[256 * 8];
    const int tid = threadIdx.x;
    const int base = blockIdx.x * 256;
    const int ro = tid >> 4, c4 = tid & 15;
    float s[4] = {0, 0, 0, 0}, s2[4] = {0, 0, 0, 0};
    for (int rr = ro; rr < 256; rr += 16) {
        int r = base + rr;
        if (r >= n2) break;
        float4 a = make_float4(0, 0, 0, 0);
        for (int t = 0; t < ntaps; ++t) {
            int p = pos[t * n2 + r];
            if (p >= 0) {
                float4 m = msg4[(size_t)p * 16 + c4];
                a.x += m.x; a.y += m.y; a.z += m.z; a.w += m.w;
            }
        }
        ((float4*)pre)[(size_t)r * 16 + c4] = a;
        s[0] += a.x; s2[0] = fmaf(a.x, a.x, s2[0]);
        s[1] += a.y; s2[1] = fmaf(a.y, a.y, s2[1]);
        s[2] += a.z; s2[2] = fmaf(a.z, a.z, s2[2]);
        s[3] += a.w; s2[3] = fmaf(a.w, a.w, s2[3]);
    }
    #pragma unroll
    for (int j = 0; j < 4; ++j) { red[tid * 8 + j] = s[j]; red[tid * 8 + 4 + j] = s2[j]; }
    __syncthreads();
    if (tid < 64) {
        int cq = tid >> 2, jj = tid & 3;
        float ts = 0, t2 = 0;
        #pragma unroll
        for (int k = 0; k < 16; ++k) {
            ts += red[(k * 16 + cq) * 8 + jj];
            t2 += red[(k * 16 + cq) * 8 + 4 + jj];
        }
        g_part[(blockIdx.x * 64 + tid) * 2]     = ts;
        g_part[(blockIdx.x * 64 + tid) * 2 + 1] = t2;
    }
}

__global__ __launch_bounds__(256)
void up_sum_kernel(const float4* __restrict__ msg4, int n2)
{
    __shared__ float red[256 * 8];
    const int tid = threadIdx.x;
    const int base = blockIdx.x * 256;
    const int ro = tid >> 4, c4 = tid & 15;
    float s[4] = {0, 0, 0, 0}, s2[4] = {0, 0, 0, 0};
    for (int rr = ro; rr < 256; rr += 16) {
        int r = base + rr;
        if (r >= n2) break;
        float4 a = msg4[(size_t)g_posup[r] * 16 + c4];
        ((float4*)g_x)[(size_t)r * 32 + c4] = a;
        s[0] += a.x; s2[0] = fmaf(a.x, a.x, s2[0]);
        s[1] += a.y; s2[1] = fmaf(a.y, a.y, s2[1]);
        s[2] += a.z; s2[2] = fmaf(a.z, a.z, s2[2]);
        s[3] += a.w; s2[3] = fmaf(a.w, a.w, s2[3]);
    }
    #pragma unroll
    for (int j = 0; j < 4; ++j) { red[tid * 8 + j] = s[j]; red[tid * 8 + 4 + j] = s2[j]; }
    __syncthreads();
    if (tid < 64) {
        int cq = tid >> 2, jj = tid & 3;
        float ts = 0, t2 = 0;
        #pragma unroll
        for (int k = 0; k < 16; ++k) {
            ts += red[(k * 16 + cq) * 8 + jj];
            t2 += red[(k * 16 + cq) * 8 + 4 + jj];
        }
        g_part[(blockIdx.x * 64 + tid) * 2]     = ts;
        g_part[(blockIdx.x * 64 + tid) * 2 + 1] = t2;
    }
}

// ---------------- BN finalize + apply + ReLU ---------------------------------
__global__ void bn_apply_kernel(const float* __restrict__ pre, int n, int istride,
                                float* __restrict__ out, int ostride,
                                const float* __restrict__ gamma,
                                const float* __restrict__ beta, int nparts)
{
    const int tid = threadIdx.x;
    const int c   = tid & 63;
    float s = 0.f, s2 = 0.f;
    for (int g = 0; g < nparts; ++g) {
        s  += g_part[(g * 64 + c) * 2];
        s2 += g_part[(g * 64 + c) * 2 + 1];
    }
    const float invn  = 1.f / (float)n;
    const float mean  = s * invn;
    const float var   = s2 * invn - mean * mean;
    const float inv   = rsqrtf(var + 1e-5f);
    const float scale = gamma[c] * inv;
    const float shift = beta[c] - mean * scale;
    const int rstep = gridDim.x * 4;
    for (int r = blockIdx.x * 4 + (tid >> 6); r < n; r += rstep) {
        float v = pre[(size_t)r * istride + c];
        v = fmaf(v, scale, shift);
        out[(size_t)r * ostride + c] = fmaxf(v, 0.f);
    }
}

// ---------------- launch ------------------------------------------------------
extern "C" void kernel_launch(void* const* d_in, const int* in_sizes, int n_in,
                              void* d_out, int out_size)
{
    const float* feats1   = (const float*)d_in[0];
    const float* feats2   = (const float*)d_in[1];
    const float* w_up     = (const float*)d_in[2];
    const float* gamma_up = (const float*)d_in[3];
    const float* beta_up  = (const float*)d_in[4];
    const float* w1       = (const float*)d_in[5];
    const float* gamma1   = (const float*)d_in[6];
    const float* beta1    = (const float*)d_in[7];
    const float* w2       = (const float*)d_in[8];
    const float* gamma2   = (const float*)d_in[9];
    const float* beta2    = (const float*)d_in[10];
    const int*   up_src   = (const int*)d_in[11];
    const int*   up_kidx  = (const int*)d_in[12];
    const int*   nbr_src  = (const int*)d_in[13];
    float*       out      = (float*)d_out;

    const int n2 = in_sizes[1] / 64;

    float *x, *h, *pre, *msg;
    int *entup, *ent, *cntup, *cnt;
    unsigned short *Bup, *B1, *B2;
    cudaGetSymbolAddress((void**)&x,     g_x);
    cudaGetSymbolAddress((void**)&h,     g_h);
    cudaGetSymbolAddress((void**)&pre,   g_pre);
    cudaGetSymbolAddress((void**)&msg,   g_msg);
    cudaGetSymbolAddress((void**)&entup, g_entup);
    cudaGetSymbolAddress((void**)&ent,   g_ent);
    cudaGetSymbolAddress((void**)&cntup, g_cntup);
    cudaGetSymbolAddress((void**)&cnt,   g_cnt);
    cudaGetSymbolAddress((void**)&Bup,   g_Bup);
    cudaGetSymbolAddress((void**)&B1,    g_B1);
    cudaGetSymbolAddress((void**)&B2,    g_B2);
    const int* pos;
    cudaGetSymbolAddress((void**)&pos,   g_pos);

    // smem: 2*(128*(CI+8)) + 2*(64*(CI+8)) bf16 + 128 ints
    const int SM128 = (2 * 128 * 136 + 2 * 64 * 136) * 2 + 512;  // 104960+512
    const int SM64  = (2 * 128 * 72  + 2 * 64 * 72 ) * 2 + 512;
    cudaFuncSetAttribute(conv_mma_kernel<128>,
                         cudaFuncAttributeMaxDynamicSharedMemorySize, SM128);
    cudaFuncSetAttribute(conv_mma_kernel<64>,
                         cudaFuncAttributeMaxDynamicSharedMemorySize, SM64);

    const int nbSum = (n2 + 255) / 256;           // 235
    const int gxA   = (n2 + 127) / 128;           // 469
    const int nbApply = 256;

    // 0: prep (zero counters, feats2 -> x cols 64..127, weight split/transpose)
    prep_kernel<<<1024, 256>>>((const float4*)feats2, w_up, w1, w2, n2);
    // 1: compaction fills
    fill_up_kernel<<<(n2 + 255) / 256, 256>>>(up_src, up_kidx, n2);
    fill_nbr_kernel<<<(27 * n2 + 255) / 256, 256>>>(nbr_src, n2);

    // upsample: MMA + gather-sum + BN
    conv_mma_kernel<128><<<dim3(gxA, 8), 256, SM128>>>(feats1, Bup, entup, cntup, msg, n2);
    up_sum_kernel<<<nbSum, 256>>>((const float4*)msg, n2);
    bn_apply_kernel<<<nbApply, 256>>>(x, n2, 128, x, 128, gamma_up, beta_up, nbSum);

    // conv1
    conv_mma_kernel<128><<<dim3(gxA, 27), 256, SM128>>>(x, B1, ent, cnt, msg, n2);
    conv_sum_kernel<<<nbSum, 256>>>((const float4*)msg, pos, 27, pre, n2);
    bn_apply_kernel<<<nbApply, 256>>>(pre, n2, 64, h, 64, gamma1, beta1, nbSum);

    // conv2 (same compaction/pos)
    conv_mma_kernel<64><<<dim3(gxA, 27), 256, SM64>>>(h, B2, ent, cnt, msg, n2);
    conv_sum_kernel<<<nbSum, 256>>>((const float4*)msg, pos, 27, out, n2);
    bn_apply_kernel<<<nbApply, 256>>>(out, n2, 64, out, 64, gamma2, beta2, nbSum);
}